// round 17
// baseline (speedup 1.0000x reference)
#include <cuda_runtime.h>
#include <cstdint>

// Chamfer distance with SHARED dot products between the two directions,
// 2-D register tiling (no cross-lane ops in the hot loop).
// array1, array2 [B=4, N=4096, D=3] fp32.
// out = (100/32768) * sum of per-point NN sq-dists (both dirs).
//
// Per unique (row q, col c) pair ONE dot serves both directions:
//   rowv = q.c - 0.5|c|^2                (3 FFMA, seeded with cw)
//   d2_row(q) = |q|^2 - 2 * max_c rowv
//   colacc(c) = max_q (rowv + qw),  qw = -0.5|q|^2   (1 FADD + 1 FMNMX)
//   d2_col(c) = -2 * colacc          (cw correction cancels: |c|^2+2cw = 0)
// -> 4 fma-pipe ops per pair-serving-both-dirs vs 6 in R16 (which saturated
// the FFMA rt=2 pipe at 88%). R13's dot-sharing failed on per-candidate
// cross-lane reduction INSIDE the loop; here each lane owns 8 FIXED cols in
// registers (col-accs lane-local forever) and rows stream from an 8 KB smem
// tile (pure broadcast LDS.128).
//
// Row-max combine: per row, 7-FMNMX tree over the lane's 8 dots, then only
// 2 shuffles (quad reduce) + 1 predicated STS into rowpart[4][512][8]
// (a full 5-shfl reduce would exceed the SM shuffle crossbar at 16 warps).
// Cross-block: keyed atomicMax (monotone uint encode; exact, order-
// independent -> deterministic; zero key = identity -> no init kernel;
// finisher resets -> graph-replay safe). Atomics only at block end.
//
// Block = 512 rows x 1024 cols, 512 thr (16 warps: g=col-group 0..3,
// s=row-slice 0..3; warp = 128 rows x 256 cols; lane = 8 cols).
// Grid 128 = 4 batches x 8 row-tiles x 4 col-tiles (one wave).
// Last block (atomic counter) decodes keys, adds |q|^2 for rows, sums.

#define BLK 512
#define NPTS 4096
#define RTILE 512
#define CTILE 1024
#define CT 8
#define NBLOCKS 128
#define NEG3 (-3.0e38f)
#define SMEM_BYTES (RTILE * 16 + 4 * RTILE * 8 * 4)   // 8 KB + 64 KB

__device__ unsigned int g_rowkey[4][NPTS];   // zero-init; self-resets
__device__ unsigned int g_colkey[4][NPTS];   // zero-init; self-resets
__device__ int          g_count;             // zero-init; self-resets

__device__ __forceinline__ unsigned int fkey(float f) {
    const unsigned int u = __float_as_uint(f);
    return u ^ ((unsigned int)(((int)u) >> 31) | 0x80000000u);
}
__device__ __forceinline__ float fdec(unsigned int k) {
    const unsigned int u = (k & 0x80000000u) ? (k ^ 0x80000000u) : ~k;
    return __uint_as_float(u);
}

__global__ __launch_bounds__(BLK) void chamfer_main(
    const float* __restrict__ a1, const float* __restrict__ a2,
    float* __restrict__ out)
{
    extern __shared__ char smem[];
    float4* srow = (float4*)smem;                                  // [512]
    float (*rowpart)[RTILE][8] =
        (float (*)[RTILE][8])(smem + RTILE * 16);                  // [4][512][8]
    __shared__ float s_red[16];
    __shared__ int   s_last;

    const int t  = threadIdx.x;
    const int wi = t >> 5, l = t & 31;
    const int g  = wi & 3;               // col group 0..3
    const int s  = wi >> 2;              // row slice 0..3
    const int b  = blockIdx.x >> 5;      // batch
    const int rt = (blockIdx.x >> 2) & 7;
    const int ct = blockIdx.x & 3;

    const float* A1 = a1 + (size_t)b * NPTS * 3;   // rows (queries of dir 2)
    const float* A2 = a2 + (size_t)b * NPTS * 3;   // cols (queries of dir 1)

    // 8 fixed candidate columns per lane, in registers
    const int c0 = ct * CTILE + g * 256 + l;
    float cx[CT], cy[CT], cz[CT], cw[CT], cacc[CT];
#pragma unroll
    for (int k = 0; k < CT; k++) {
        const int c = c0 + k * 32;
        cx[k] = A2[c * 3 + 0];
        cy[k] = A2[c * 3 + 1];
        cz[k] = A2[c * 3 + 2];
        cw[k] = -0.5f * (cx[k] * cx[k] + cy[k] * cy[k] + cz[k] * cz[k]);
        cacc[k] = NEG3;
    }

    // fill row tile: 512 rows of a1 with qw = -0.5|q|^2
    if (t < 128) {
        const float4* rsrc = (const float4*)(A1 + (size_t)rt * RTILE * 3);
        const float4 A = rsrc[t * 3 + 0];
        const float4 B = rsrc[t * 3 + 1];
        const float4 C = rsrc[t * 3 + 2];
        srow[t * 4 + 0] = make_float4(A.x, A.y, A.z,
            -0.5f * (A.x * A.x + A.y * A.y + A.z * A.z));
        srow[t * 4 + 1] = make_float4(A.w, B.x, B.y,
            -0.5f * (A.w * A.w + B.x * B.x + B.y * B.y));
        srow[t * 4 + 2] = make_float4(B.z, B.w, C.x,
            -0.5f * (B.z * B.z + B.w * B.w + C.x * C.x));
        srow[t * 4 + 3] = make_float4(C.y, C.z, C.w,
            -0.5f * (C.y * C.y + C.z * C.z + C.w * C.w));
    }
    __syncthreads();

    // hot loop: this warp's 128 rows x its lane's 8 cols
    const float4* rp = srow + s * 128;
    float* rpart = &rowpart[g][s * 128][0];
#pragma unroll 2
    for (int i = 0; i < 128; i++) {
        const float4 q = rp[i];          // broadcast LDS.128
        float tv[CT];
#pragma unroll
        for (int k = 0; k < CT; k++) {
            tv[k] = fmaf(q.x, cx[k], fmaf(q.y, cy[k], fmaf(q.z, cz[k], cw[k])));
            cacc[k] = fmaxf(cacc[k], tv[k] + q.w);
        }
        const float r01 = fmaxf(tv[0], tv[1]);
        const float r23 = fmaxf(tv[2], tv[3]);
        const float r45 = fmaxf(tv[4], tv[5]);
        const float r67 = fmaxf(tv[6], tv[7]);
        float rm = fmaxf(fmaxf(r01, r23), fmaxf(r45, r67));
        rm = fmaxf(rm, __shfl_xor_sync(0xffffffffu, rm, 1));
        rm = fmaxf(rm, __shfl_xor_sync(0xffffffffu, rm, 2));
        if ((l & 3) == 0) rpart[i * 8 + (l >> 2)] = rm;
    }
    __syncthreads();

    // row combine: thread t owns row t; max over 4 groups x 8 quad-slots
    {
        float rv = NEG3;
#pragma unroll
        for (int gg = 0; gg < 4; gg++)
#pragma unroll
            for (int j = 0; j < 8; j++)
                rv = fmaxf(rv, rowpart[gg][t][j]);
        atomicMax(&g_rowkey[b][rt * RTILE + t], fkey(rv));
    }
    // col atomics: 4 warps sharing each col merge via atomicMax
#pragma unroll
    for (int k = 0; k < CT; k++)
        atomicMax(&g_colkey[b][c0 + k * 32], fkey(cacc[k]));

    if (t == 0) {
        __threadfence();
        s_last = (atomicAdd(&g_count, 1) == NBLOCKS - 1);
    }
    __syncthreads();
    if (!s_last) return;
    __threadfence();

    // ---- finisher: decode + sum in fixed order -> deterministic ----
    float acc = 0.0f;
#pragma unroll 1
    for (int j = 0; j < 8; j++) {
        const int r = t + j * BLK;
#pragma unroll
        for (int b2 = 0; b2 < 4; b2++) {
            const float x = a1[(size_t)b2 * NPTS * 3 + r * 3 + 0];
            const float y = a1[(size_t)b2 * NPTS * 3 + r * 3 + 1];
            const float z = a1[(size_t)b2 * NPTS * 3 + r * 3 + 2];
            acc += (x * x + y * y + z * z) - 2.0f * fdec(g_rowkey[b2][r]);
            acc += -2.0f * fdec(g_colkey[b2][r]);
            g_rowkey[b2][r] = 0u;        // reset for next graph replay
            g_colkey[b2][r] = 0u;
        }
    }
#pragma unroll
    for (int o = 16; o; o >>= 1) acc += __shfl_xor_sync(0xffffffffu, acc, o);
    if (l == 0) s_red[wi] = acc;
    __syncthreads();

    if (t == 0) {
        float ss = 0.0f;
#pragma unroll
        for (int gg = 0; gg < 16; gg++) ss += s_red[gg];
        out[0] = ss * (100.0f / 32768.0f);
        g_count = 0;                     // reset for next graph replay
    }
}

extern "C" void kernel_launch(void* const* d_in, const int* in_sizes, int n_in,
                              void* d_out, int out_size)
{
    const float* a1 = (const float*)d_in[0];
    const float* a2 = (const float*)d_in[1];
    float* out = (float*)d_out;

    cudaFuncSetAttribute(chamfer_main,
                         cudaFuncAttributeMaxDynamicSharedMemorySize,
                         SMEM_BYTES);

    chamfer_main<<<NBLOCKS, BLK, SMEM_BYTES>>>(a1, a2, out);
}